// round 13
// baseline (speedup 1.0000x reference)
#include <cuda_runtime.h>

#define NN 50000
#define EE 800000
#define HEADS 8
#define INF 256
#define OUTF 256
#define NEG 0.2f
#define LNEPS 1e-5f
#define SCAN_BLK 1024
#define NSCAN ((NN + SCAN_BLK - 1) / SCAN_BLK)   // 49

typedef unsigned long long ull;

// ---------------- scratch (device globals) -----------------------------------
__device__ float g_h[(size_t)NN * OUTF];        // x @ W  (51.2 MB, L2-resident)
__device__ float g_asrc[NN * HEADS];
__device__ float g_adst[NN * HEADS];
__device__ int   g_deg[NN];
__device__ int   g_start[NN + 1];
__device__ int   g_cursor[NN];
__device__ int   g_part[NSCAN];
__device__ int   g_csr[EE];                     // SRC ids bucketed by dst (real edges only)

// ---------------- GEMM: h = x @ W + fused att (non-atomic: unique writer) ----
__global__ void __launch_bounds__(256, 2) gemm_kernel(const float* __restrict__ X,
                                                      const float* __restrict__ W,
                                                      const float* __restrict__ att_src,
                                                      const float* __restrict__ att_dst) {
    __shared__ float As[16][132];   // [k][m], transposed A
    __shared__ float Bs[16][132];   // [k][n]

    int tid = threadIdx.x;
    int tx = tid & 15, ty = tid >> 4;
    int row0 = blockIdx.x * 128;
    int col0 = blockIdx.y * 128;

    int ra0 = tid >> 2,  qa0 = tid & 3;                 // X slot 0
    int ra1 = (tid + 256) >> 2, qa1 = tid & 3;          // X slot 1
    int kb0 = tid >> 5,  nb0 = tid & 31;                // W slot 0
    int kb1 = (tid + 256) >> 5, nb1 = tid & 31;         // W slot 1

    ull acc[8][4] = {};
    float4 xa[2], wb[2];

    // preload k0 = 0
    {
        xa[0] = make_float4(0.f,0.f,0.f,0.f);
        xa[1] = make_float4(0.f,0.f,0.f,0.f);
        if (row0 + ra0 < NN) xa[0] = *(const float4*)&X[(size_t)(row0 + ra0) * INF + qa0 * 4];
        if (row0 + ra1 < NN) xa[1] = *(const float4*)&X[(size_t)(row0 + ra1) * INF + qa1 * 4];
        wb[0] = *(const float4*)&W[(size_t)kb0 * OUTF + col0 + nb0 * 4];
        wb[1] = *(const float4*)&W[(size_t)kb1 * OUTF + col0 + nb1 * 4];
    }

    for (int k0 = 0; k0 < INF; k0 += 16) {
        As[qa0 * 4 + 0][ra0] = xa[0].x; As[qa0 * 4 + 1][ra0] = xa[0].y;
        As[qa0 * 4 + 2][ra0] = xa[0].z; As[qa0 * 4 + 3][ra0] = xa[0].w;
        As[qa1 * 4 + 0][ra1] = xa[1].x; As[qa1 * 4 + 1][ra1] = xa[1].y;
        As[qa1 * 4 + 2][ra1] = xa[1].z; As[qa1 * 4 + 3][ra1] = xa[1].w;
        *(float4*)&Bs[kb0][nb0 * 4] = wb[0];
        *(float4*)&Bs[kb1][nb1 * 4] = wb[1];
        __syncthreads();

        int kn = k0 + 16;
        if (kn < INF) {
            xa[0] = make_float4(0.f,0.f,0.f,0.f);
            xa[1] = make_float4(0.f,0.f,0.f,0.f);
            if (row0 + ra0 < NN) xa[0] = *(const float4*)&X[(size_t)(row0 + ra0) * INF + kn + qa0 * 4];
            if (row0 + ra1 < NN) xa[1] = *(const float4*)&X[(size_t)(row0 + ra1) * INF + kn + qa1 * 4];
            wb[0] = *(const float4*)&W[(size_t)(kn + kb0) * OUTF + col0 + nb0 * 4];
            wb[1] = *(const float4*)&W[(size_t)(kn + kb1) * OUTF + col0 + nb1 * 4];
        }

        #pragma unroll
        for (int k = 0; k < 16; k++) {
            ull b[4];
            {
                ulonglong2 b01 = *(const ulonglong2*)&Bs[k][tx * 4];
                ulonglong2 b23 = *(const ulonglong2*)&Bs[k][tx * 4 + 64];
                b[0] = b01.x; b[1] = b01.y; b[2] = b23.x; b[3] = b23.y;
            }
            float4 alo = *(const float4*)&As[k][ty * 4];
            float4 ahi = *(const float4*)&As[k][ty * 4 + 64];
            float av[8] = { alo.x, alo.y, alo.z, alo.w, ahi.x, ahi.y, ahi.z, ahi.w };
            #pragma unroll
            for (int mi = 0; mi < 8; mi++) {
                ull ad;
                asm("mov.b64 %0, {%1, %1};" : "=l"(ad) : "f"(av[mi]));
                #pragma unroll
                for (int p = 0; p < 4; p++)
                    asm("fma.rn.f32x2 %0, %1, %2, %0;" : "+l"(acc[mi][p]) : "l"(ad), "l"(b[p]));
            }
        }
        __syncthreads();
    }

    // att vectors for this thread's 8 columns
    float4 as0 = *(const float4*)&att_src[col0 + tx * 4];
    float4 as1 = *(const float4*)&att_src[col0 + tx * 4 + 64];
    float4 ad0 = *(const float4*)&att_dst[col0 + tx * 4];
    float4 ad1 = *(const float4*)&att_dst[col0 + tx * 4 + 64];
    int head_lo = (col0 >> 5) + (tx >> 3);
    int head_hi = head_lo + 2;

    #pragma unroll
    for (int mi = 0; mi < 8; mi++) {
        int r = row0 + (mi < 4 ? ty * 4 + mi : 64 + ty * 4 + mi - 4);
        float4 lo, hi;
        asm("mov.b64 {%0, %1}, %2;" : "=f"(lo.x), "=f"(lo.y) : "l"(acc[mi][0]));
        asm("mov.b64 {%0, %1}, %2;" : "=f"(lo.z), "=f"(lo.w) : "l"(acc[mi][1]));
        asm("mov.b64 {%0, %1}, %2;" : "=f"(hi.x), "=f"(hi.y) : "l"(acc[mi][2]));
        asm("mov.b64 {%0, %1}, %2;" : "=f"(hi.z), "=f"(hi.w) : "l"(acc[mi][3]));

        // per-head dot partials; 8-lane xor reduction covers the head's full 32 cols
        float ps = lo.x * as0.x + lo.y * as0.y + lo.z * as0.z + lo.w * as0.w;
        float ph = hi.x * as1.x + hi.y * as1.y + hi.z * as1.z + hi.w * as1.w;
        float ds = lo.x * ad0.x + lo.y * ad0.y + lo.z * ad0.z + lo.w * ad0.w;
        float dh = hi.x * ad1.x + hi.y * ad1.y + hi.z * ad1.z + hi.w * ad1.w;
        #pragma unroll
        for (int o = 1; o <= 4; o <<= 1) {
            ps += __shfl_xor_sync(0xffffffffu, ps, o);
            ph += __shfl_xor_sync(0xffffffffu, ph, o);
            ds += __shfl_xor_sync(0xffffffffu, ds, o);
            dh += __shfl_xor_sync(0xffffffffu, dh, o);
        }

        if (r < NN) {
            *(float4*)&g_h[(size_t)r * OUTF + col0 + tx * 4]      = lo;
            *(float4*)&g_h[(size_t)r * OUTF + col0 + tx * 4 + 64] = hi;
            if ((tx & 7) == 0) {     // unique writer per (r, head): plain stores
                g_asrc[r * HEADS + head_lo] = ps;
                g_asrc[r * HEADS + head_hi] = ph;
                g_adst[r * HEADS + head_lo] = ds;
                g_adst[r * HEADS + head_hi] = dh;
            }
        }
    }
}

// ---------------- CSR build (real edges only; self-loops implicit) ----------
__global__ void zero_deg_kernel() {
    int i = blockIdx.x * blockDim.x + threadIdx.x;
    if (i < NN) g_deg[i] = 0;
}

__global__ void count_kernel(const int* __restrict__ ei) {
    int t = blockIdx.x * blockDim.x + threadIdx.x;
    int e4 = t * 4;
    if (e4 >= EE) return;
    int4 d4 = *(const int4*)&ei[EE + e4];
    atomicAdd(&g_deg[d4.x], 1);
    atomicAdd(&g_deg[d4.y], 1);
    atomicAdd(&g_deg[d4.z], 1);
    atomicAdd(&g_deg[d4.w], 1);
}

__global__ void scan1_kernel() {
    int tid = threadIdx.x;
    int lane = tid & 31, w = tid >> 5;
    int i = blockIdx.x * SCAN_BLK + tid;
    __shared__ int wsum[32];

    int v = (i < NN) ? g_deg[i] : 0;
    int x = v;
    #pragma unroll
    for (int o = 1; o < 32; o <<= 1) {
        int y = __shfl_up_sync(0xffffffffu, x, o);
        if (lane >= o) x += y;
    }
    if (lane == 31) wsum[w] = x;
    __syncthreads();
    if (w == 0) {
        int y = wsum[lane];
        #pragma unroll
        for (int o = 1; o < 32; o <<= 1) {
            int z = __shfl_up_sync(0xffffffffu, y, o);
            if (lane >= o) y += z;
        }
        wsum[lane] = y;
    }
    __syncthreads();
    int incl = x + (w > 0 ? wsum[w - 1] : 0);
    if (i < NN) g_start[i] = incl - v;        // local exclusive
    if (tid == SCAN_BLK - 1) g_part[blockIdx.x] = incl;
}

__global__ void scan2_kernel() {
    int tid = threadIdx.x;                    // 64 threads
    int lane = tid & 31, w = tid >> 5;
    __shared__ int wsum[2];
    int v = (tid < NSCAN) ? g_part[tid] : 0;
    int x = v;
    #pragma unroll
    for (int o = 1; o < 32; o <<= 1) {
        int y = __shfl_up_sync(0xffffffffu, x, o);
        if (lane >= o) x += y;
    }
    if (lane == 31) wsum[w] = x;
    __syncthreads();
    int incl = x + (w > 0 ? wsum[0] : 0);
    if (tid < NSCAN) g_part[tid] = incl - v;  // exclusive
    if (tid == NSCAN - 1) g_start[NN] = incl; // total = EE
}

__global__ void scan3_kernel() {
    int i = blockIdx.x * blockDim.x + threadIdx.x;
    if (i >= NN) return;
    int s = g_start[i] + g_part[i >> 10];
    g_start[i] = s;
    g_cursor[i] = s;
}

__global__ void fill_kernel(const int* __restrict__ ei) {
    int t = blockIdx.x * blockDim.x + threadIdx.x;
    int e4 = t * 4;
    if (e4 >= EE) return;
    int4 s4 = *(const int4*)&ei[e4];
    int4 d4 = *(const int4*)&ei[EE + e4];
    g_csr[atomicAdd(&g_cursor[d4.x], 1)] = s4.x;
    g_csr[atomicAdd(&g_cursor[d4.y], 1)] = s4.y;
    g_csr[atomicAdd(&g_cursor[d4.z], 1)] = s4.z;
    g_csr[atomicAdd(&g_cursor[d4.w], 1)] = s4.w;
}

// ---------- fused aggregate + softmax + bias + LN + ReLU (2 cols/thread) -----
__global__ void __launch_bounds__(128) agg_ln_kernel(float* __restrict__ out,
                              const float* __restrict__ bias,
                              const float* __restrict__ gamma,
                              const float* __restrict__ beta) {
    int d = blockIdx.x;                 // dst node
    int c2 = threadIdx.x;               // column pair 0..127 -> cols 2c2, 2c2+1
    int head = c2 >> 4;                 // 16 pairs per head
    int lane = c2 & 31, w = c2 >> 5;

    int beg = g_start[d], end = g_start[d + 1];

    // implicit self-loop seeds the accumulators (guarantees den > 0)
    float es = g_asrc[d * HEADS + head] + g_adst[d * HEADS + head];
    es = es > 0.f ? es : NEG * es;
    float exs = __expf(es);
    float den = exs;
    float2 hs = *(const float2*)&g_h[(size_t)d * OUTF + c2 * 2];
    float accx = exs * hs.x, accy = exs * hs.y;

    __shared__ int   s_src[64];
    __shared__ float s_ex[64 * HEADS];  // [j][h]

    for (int base = beg; base < end; base += 64) {
        int nb = end - base; if (nb > 64) nb = 64;
        #pragma unroll
        for (int t = 0; t < 4; t++) {
            int idx = c2 + t * 128;
            if (idx < nb * HEADS) {
                int j = idx >> 3, h = idx & 7;
                int src = g_csr[base + j];
                if (h == 0) s_src[j] = src;
                float e = g_asrc[src * HEADS + h] + g_adst[d * HEADS + h];
                e = e > 0.f ? e : NEG * e;
                s_ex[idx] = __expf(e);
            }
        }
        __syncthreads();

        int j = 0;
        for (; j + 8 <= nb; j += 8) {
            int sj[8]; float ej[8]; float2 hj[8];
            #pragma unroll
            for (int u = 0; u < 8; u++) {
                sj[u] = s_src[j + u];
                ej[u] = s_ex[(j + u) * HEADS + head];
            }
            #pragma unroll
            for (int u = 0; u < 8; u++)
                hj[u] = *(const float2*)&g_h[(size_t)sj[u] * OUTF + c2 * 2];
            #pragma unroll
            for (int u = 0; u < 8; u++) {
                accx += ej[u] * hj[u].x; accy += ej[u] * hj[u].y; den += ej[u];
            }
        }
        for (; j < nb; j++) {
            int s0 = s_src[j];
            float e0 = s_ex[j * HEADS + head];
            float2 h0 = *(const float2*)&g_h[(size_t)s0 * OUTF + c2 * 2];
            accx += e0 * h0.x; accy += e0 * h0.y; den += e0;
        }
        __syncthreads();
    }

    float rden = 1.f / den;
    float2 bi = *(const float2*)&bias[c2 * 2];
    float v0 = accx * rden + bi.x;
    float v1 = accy * rden + bi.y;

    // LayerNorm over 256 + ReLU (4 warps)
    __shared__ float ssum[4], ssq[4];
    float s = v0 + v1, q = v0 * v0 + v1 * v1;
    #pragma unroll
    for (int o = 16; o; o >>= 1) {
        s += __shfl_down_sync(0xffffffffu, s, o);
        q += __shfl_down_sync(0xffffffffu, q, o);
    }
    if (lane == 0) { ssum[w] = s; ssq[w] = q; }
    __syncthreads();

    __shared__ float mean_s, rstd_s;
    if (c2 == 0) {
        float S = ssum[0] + ssum[1] + ssum[2] + ssum[3];
        float Q = ssq[0] + ssq[1] + ssq[2] + ssq[3];
        float mu = S * (1.f / OUTF);
        float var = Q * (1.f / OUTF) - mu * mu;
        mean_s = mu;
        rstd_s = rsqrtf(var + LNEPS);
    }
    __syncthreads();

    float2 ga = *(const float2*)&gamma[c2 * 2];
    float2 be = *(const float2*)&beta[c2 * 2];
    float y0 = (v0 - mean_s) * rstd_s * ga.x + be.x;
    float y1 = (v1 - mean_s) * rstd_s * ga.y + be.y;
    float2 res = make_float2(fmaxf(y0, 0.f), fmaxf(y1, 0.f));
    *(float2*)&out[(size_t)d * OUTF + c2 * 2] = res;
}

// ---------------- launch (fork-join: CSR build overlaps GEMM) ----------------
static cudaStream_t g_s2 = 0;
static cudaEvent_t  g_evA = 0, g_evB = 0;

extern "C" void kernel_launch(void* const* d_in, const int* in_sizes, int n_in,
                              void* d_out, int out_size) {
    const float* x       = (const float*)d_in[0];
    const int*   ei      = (const int*)d_in[1];
    const float* W       = (const float*)d_in[2];
    const float* att_src = (const float*)d_in[3];
    const float* att_dst = (const float*)d_in[4];
    const float* bias    = (const float*)d_in[5];
    const float* gamma   = (const float*)d_in[6];
    const float* beta    = (const float*)d_in[7];
    float* out = (float*)d_out;

    if (!g_s2) {   // host-side resources only; created on the uncaptured first call
        cudaStreamCreateWithFlags(&g_s2, cudaStreamNonBlocking);
        cudaEventCreateWithFlags(&g_evA, cudaEventDisableTiming);
        cudaEventCreateWithFlags(&g_evB, cudaEventDisableTiming);
    }

    // fork from the capture-origin stream
    cudaEventRecord(g_evA, 0);

    // side stream: CSR build (depends only on edge_index)
    cudaStreamWaitEvent(g_s2, g_evA, 0);
    zero_deg_kernel<<<(NN + 255) / 256, 256, 0, g_s2>>>();
    count_kernel<<<(EE / 4 + 255) / 256, 256, 0, g_s2>>>(ei);
    scan1_kernel<<<NSCAN, SCAN_BLK, 0, g_s2>>>();
    scan2_kernel<<<1, 64, 0, g_s2>>>();
    scan3_kernel<<<(NN + 255) / 256, 256, 0, g_s2>>>();
    fill_kernel<<<(EE / 4 + 255) / 256, 256, 0, g_s2>>>(ei);
    cudaEventRecord(g_evB, g_s2);

    // main stream: GEMM with fused att reduction (overlaps CSR build)
    dim3 gg((NN + 127) / 128, OUTF / 128);
    gemm_kernel<<<gg, 256>>>(x, W, att_src, att_dst);

    // join, then fused aggregate+softmax+LN
    cudaStreamWaitEvent(0, g_evB, 0);
    agg_ln_kernel<<<NN, 128>>>(out, bias, gamma, beta);
}

// round 14
// speedup vs baseline: 1.0445x; 1.0445x over previous
#include <cuda_runtime.h>

#define NN 50000
#define EE 800000
#define HEADS 8
#define INF 256
#define OUTF 256
#define NEG 0.2f
#define LNEPS 1e-5f
#define SCAN_BLK 1024
#define NSCAN ((NN + SCAN_BLK - 1) / SCAN_BLK)   // 49

typedef unsigned long long ull;

// ---------------- scratch (device globals) -----------------------------------
__device__ float g_h[(size_t)NN * OUTF];        // x @ W  (51.2 MB, L2-resident)
__device__ float g_asrc[NN * HEADS];
__device__ float g_adst[NN * HEADS];
__device__ int   g_deg[NN];
__device__ int   g_start[NN + 1];
__device__ int   g_cursor[NN];
__device__ int   g_part[NSCAN];
__device__ int   g_csr[EE];                     // SRC ids bucketed by dst (real edges only)

// ---------------- GEMM: h = x @ W + fused att (double-buffered, 1 sync/iter) -
__global__ void __launch_bounds__(256, 2) gemm_kernel(const float* __restrict__ X,
                                                      const float* __restrict__ W,
                                                      const float* __restrict__ att_src,
                                                      const float* __restrict__ att_dst) {
    __shared__ float As[2][16][132];   // [buf][k][m]
    __shared__ float Bs[2][16][132];   // [buf][k][n]

    int tid = threadIdx.x;
    int tx = tid & 15, ty = tid >> 4;
    int row0 = blockIdx.x * 128;
    int col0 = blockIdx.y * 128;

    int ra0 = tid >> 2,  qa0 = tid & 3;                 // X slot 0
    int ra1 = (tid + 256) >> 2, qa1 = tid & 3;          // X slot 1
    int kb0 = tid >> 5,  nb0 = tid & 31;                // W slot 0
    int kb1 = (tid + 256) >> 5, nb1 = tid & 31;         // W slot 1

    ull acc[8][4] = {};
    float4 xa[2], wb[2];

    // preload + stage k0 = 0 into buf 0
    {
        xa[0] = make_float4(0.f,0.f,0.f,0.f);
        xa[1] = make_float4(0.f,0.f,0.f,0.f);
        if (row0 + ra0 < NN) xa[0] = *(const float4*)&X[(size_t)(row0 + ra0) * INF + qa0 * 4];
        if (row0 + ra1 < NN) xa[1] = *(const float4*)&X[(size_t)(row0 + ra1) * INF + qa1 * 4];
        wb[0] = *(const float4*)&W[(size_t)kb0 * OUTF + col0 + nb0 * 4];
        wb[1] = *(const float4*)&W[(size_t)kb1 * OUTF + col0 + nb1 * 4];
        As[0][qa0 * 4 + 0][ra0] = xa[0].x; As[0][qa0 * 4 + 1][ra0] = xa[0].y;
        As[0][qa0 * 4 + 2][ra0] = xa[0].z; As[0][qa0 * 4 + 3][ra0] = xa[0].w;
        As[0][qa1 * 4 + 0][ra1] = xa[1].x; As[0][qa1 * 4 + 1][ra1] = xa[1].y;
        As[0][qa1 * 4 + 2][ra1] = xa[1].z; As[0][qa1 * 4 + 3][ra1] = xa[1].w;
        *(float4*)&Bs[0][kb0][nb0 * 4] = wb[0];
        *(float4*)&Bs[0][kb1][nb1 * 4] = wb[1];
    }
    __syncthreads();

    #pragma unroll 1
    for (int it = 0; it < 16; it++) {
        int cur = it & 1, nxt = cur ^ 1;
        int kn = (it + 1) * 16;
        if (kn < INF) {    // prefetch next tile into registers (latency overlaps compute)
            xa[0] = make_float4(0.f,0.f,0.f,0.f);
            xa[1] = make_float4(0.f,0.f,0.f,0.f);
            if (row0 + ra0 < NN) xa[0] = *(const float4*)&X[(size_t)(row0 + ra0) * INF + kn + qa0 * 4];
            if (row0 + ra1 < NN) xa[1] = *(const float4*)&X[(size_t)(row0 + ra1) * INF + kn + qa1 * 4];
            wb[0] = *(const float4*)&W[(size_t)(kn + kb0) * OUTF + col0 + nb0 * 4];
            wb[1] = *(const float4*)&W[(size_t)(kn + kb1) * OUTF + col0 + nb1 * 4];
        }

        #pragma unroll
        for (int k = 0; k < 16; k++) {
            ull b[4];
            {
                ulonglong2 b01 = *(const ulonglong2*)&Bs[cur][k][tx * 4];
                ulonglong2 b23 = *(const ulonglong2*)&Bs[cur][k][tx * 4 + 64];
                b[0] = b01.x; b[1] = b01.y; b[2] = b23.x; b[3] = b23.y;
            }
            float4 alo = *(const float4*)&As[cur][k][ty * 4];
            float4 ahi = *(const float4*)&As[cur][k][ty * 4 + 64];
            float av[8] = { alo.x, alo.y, alo.z, alo.w, ahi.x, ahi.y, ahi.z, ahi.w };
            #pragma unroll
            for (int mi = 0; mi < 8; mi++) {
                ull ad;
                asm("mov.b64 %0, {%1, %1};" : "=l"(ad) : "f"(av[mi]));
                #pragma unroll
                for (int p = 0; p < 4; p++)
                    asm("fma.rn.f32x2 %0, %1, %2, %0;" : "+l"(acc[mi][p]) : "l"(ad), "l"(b[p]));
            }
        }

        if (kn < INF) {    // store prefetched regs into the other buffer; single sync
            As[nxt][qa0 * 4 + 0][ra0] = xa[0].x; As[nxt][qa0 * 4 + 1][ra0] = xa[0].y;
            As[nxt][qa0 * 4 + 2][ra0] = xa[0].z; As[nxt][qa0 * 4 + 3][ra0] = xa[0].w;
            As[nxt][qa1 * 4 + 0][ra1] = xa[1].x; As[nxt][qa1 * 4 + 1][ra1] = xa[1].y;
            As[nxt][qa1 * 4 + 2][ra1] = xa[1].z; As[nxt][qa1 * 4 + 3][ra1] = xa[1].w;
            *(float4*)&Bs[nxt][kb0][nb0 * 4] = wb[0];
            *(float4*)&Bs[nxt][kb1][nb1 * 4] = wb[1];
            __syncthreads();
        }
    }

    // att vectors for this thread's 8 columns
    float4 as0 = *(const float4*)&att_src[col0 + tx * 4];
    float4 as1 = *(const float4*)&att_src[col0 + tx * 4 + 64];
    float4 ad0 = *(const float4*)&att_dst[col0 + tx * 4];
    float4 ad1 = *(const float4*)&att_dst[col0 + tx * 4 + 64];
    int head_lo = (col0 >> 5) + (tx >> 3);
    int head_hi = head_lo + 2;

    #pragma unroll
    for (int mi = 0; mi < 8; mi++) {
        int r = row0 + (mi < 4 ? ty * 4 + mi : 64 + ty * 4 + mi - 4);
        float4 lo, hi;
        asm("mov.b64 {%0, %1}, %2;" : "=f"(lo.x), "=f"(lo.y) : "l"(acc[mi][0]));
        asm("mov.b64 {%0, %1}, %2;" : "=f"(lo.z), "=f"(lo.w) : "l"(acc[mi][1]));
        asm("mov.b64 {%0, %1}, %2;" : "=f"(hi.x), "=f"(hi.y) : "l"(acc[mi][2]));
        asm("mov.b64 {%0, %1}, %2;" : "=f"(hi.z), "=f"(hi.w) : "l"(acc[mi][3]));

        float ps = lo.x * as0.x + lo.y * as0.y + lo.z * as0.z + lo.w * as0.w;
        float ph = hi.x * as1.x + hi.y * as1.y + hi.z * as1.z + hi.w * as1.w;
        float ds = lo.x * ad0.x + lo.y * ad0.y + lo.z * ad0.z + lo.w * ad0.w;
        float dh = hi.x * ad1.x + hi.y * ad1.y + hi.z * ad1.z + hi.w * ad1.w;
        #pragma unroll
        for (int o = 1; o <= 4; o <<= 1) {
            ps += __shfl_xor_sync(0xffffffffu, ps, o);
            ph += __shfl_xor_sync(0xffffffffu, ph, o);
            ds += __shfl_xor_sync(0xffffffffu, ds, o);
            dh += __shfl_xor_sync(0xffffffffu, dh, o);
        }

        if (r < NN) {
            *(float4*)&g_h[(size_t)r * OUTF + col0 + tx * 4]      = lo;
            *(float4*)&g_h[(size_t)r * OUTF + col0 + tx * 4 + 64] = hi;
            if ((tx & 7) == 0) {
                g_asrc[r * HEADS + head_lo] = ps;
                g_asrc[r * HEADS + head_hi] = ph;
                g_adst[r * HEADS + head_lo] = ds;
                g_adst[r * HEADS + head_hi] = dh;
            }
        }
    }
}

// ---------------- CSR build (real edges only; self-loops implicit) ----------
__global__ void zero_deg_kernel() {
    int i = blockIdx.x * blockDim.x + threadIdx.x;
    if (i < NN) g_deg[i] = 0;
}

__global__ void count_kernel(const int* __restrict__ ei) {
    int t = blockIdx.x * blockDim.x + threadIdx.x;
    int e4 = t * 4;
    if (e4 >= EE) return;
    int4 d4 = *(const int4*)&ei[EE + e4];
    atomicAdd(&g_deg[d4.x], 1);
    atomicAdd(&g_deg[d4.y], 1);
    atomicAdd(&g_deg[d4.z], 1);
    atomicAdd(&g_deg[d4.w], 1);
}

__global__ void scan1_kernel() {
    int tid = threadIdx.x;
    int lane = tid & 31, w = tid >> 5;
    int i = blockIdx.x * SCAN_BLK + tid;
    __shared__ int wsum[32];

    int v = (i < NN) ? g_deg[i] : 0;
    int x = v;
    #pragma unroll
    for (int o = 1; o < 32; o <<= 1) {
        int y = __shfl_up_sync(0xffffffffu, x, o);
        if (lane >= o) x += y;
    }
    if (lane == 31) wsum[w] = x;
    __syncthreads();
    if (w == 0) {
        int y = wsum[lane];
        #pragma unroll
        for (int o = 1; o < 32; o <<= 1) {
            int z = __shfl_up_sync(0xffffffffu, y, o);
            if (lane >= o) y += z;
        }
        wsum[lane] = y;
    }
    __syncthreads();
    int incl = x + (w > 0 ? wsum[w - 1] : 0);
    if (i < NN) g_start[i] = incl - v;        // local exclusive
    if (tid == SCAN_BLK - 1) g_part[blockIdx.x] = incl;
}

__global__ void scan2_kernel() {
    int tid = threadIdx.x;                    // 64 threads
    int lane = tid & 31, w = tid >> 5;
    __shared__ int wsum[2];
    int v = (tid < NSCAN) ? g_part[tid] : 0;
    int x = v;
    #pragma unroll
    for (int o = 1; o < 32; o <<= 1) {
        int y = __shfl_up_sync(0xffffffffu, x, o);
        if (lane >= o) x += y;
    }
    if (lane == 31) wsum[w] = x;
    __syncthreads();
    int incl = x + (w > 0 ? wsum[0] : 0);
    if (tid < NSCAN) g_part[tid] = incl - v;  // exclusive
    if (tid == NSCAN - 1) g_start[NN] = incl; // total = EE
}

__global__ void scan3_kernel() {
    int i = blockIdx.x * blockDim.x + threadIdx.x;
    if (i >= NN) return;
    int s = g_start[i] + g_part[i >> 10];
    g_start[i] = s;
    g_cursor[i] = s;
}

__global__ void fill_kernel(const int* __restrict__ ei) {
    int t = blockIdx.x * blockDim.x + threadIdx.x;
    int e4 = t * 4;
    if (e4 >= EE) return;
    int4 s4 = *(const int4*)&ei[e4];
    int4 d4 = *(const int4*)&ei[EE + e4];
    g_csr[atomicAdd(&g_cursor[d4.x], 1)] = s4.x;
    g_csr[atomicAdd(&g_cursor[d4.y], 1)] = s4.y;
    g_csr[atomicAdd(&g_cursor[d4.z], 1)] = s4.z;
    g_csr[atomicAdd(&g_cursor[d4.w], 1)] = s4.w;
}

// ---------- warp-per-node aggregate + softmax + bias + LN + ReLU -------------
// lane l owns cols [l*8, l*8+8); head of lane = l>>2. No smem, no block syncs.
__global__ void __launch_bounds__(256) agg_ln_kernel(float* __restrict__ out,
                              const float* __restrict__ bias,
                              const float* __restrict__ gamma,
                              const float* __restrict__ beta) {
    int d = blockIdx.x * 8 + (threadIdx.x >> 5);
    if (d >= NN) return;
    int lane = threadIdx.x & 31;
    int h8 = lane & 7;            // head slot this lane computes exp for
    int myhead = lane >> 2;       // head owning this lane's 8 columns
    int cb = lane * 8;

    float adl = __ldg(&g_adst[d * HEADS + h8]);

    // self-loop seed
    float e0 = __ldg(&g_asrc[d * HEADS + h8]) + adl;
    e0 = e0 > 0.f ? e0 : NEG * e0;
    float ex0 = __expf(e0);
    float myex = __shfl_sync(0xffffffffu, ex0, myhead);
    float den = myex;

    float4 acc0, acc1;
    {
        float4 hv0 = *(const float4*)&g_h[(size_t)d * OUTF + cb];
        float4 hv1 = *(const float4*)&g_h[(size_t)d * OUTF + cb + 4];
        acc0 = make_float4(myex * hv0.x, myex * hv0.y, myex * hv0.z, myex * hv0.w);
        acc1 = make_float4(myex * hv1.x, myex * hv1.y, myex * hv1.z, myex * hv1.w);
    }

    int j = g_start[d], end = g_start[d + 1];
    for (; j + 4 <= end; j += 4) {
        int s0 = __ldg(&g_csr[j]);
        int s1 = __ldg(&g_csr[j + 1]);
        int s2 = __ldg(&g_csr[j + 2]);
        int s3 = __ldg(&g_csr[j + 3]);
        float a0 = __ldg(&g_asrc[s0 * HEADS + h8]) + adl;
        float a1 = __ldg(&g_asrc[s1 * HEADS + h8]) + adl;
        float a2 = __ldg(&g_asrc[s2 * HEADS + h8]) + adl;
        float a3 = __ldg(&g_asrc[s3 * HEADS + h8]) + adl;
        a0 = a0 > 0.f ? a0 : NEG * a0;  a1 = a1 > 0.f ? a1 : NEG * a1;
        a2 = a2 > 0.f ? a2 : NEG * a2;  a3 = a3 > 0.f ? a3 : NEG * a3;
        float x0 = __expf(a0), x1 = __expf(a1), x2 = __expf(a2), x3 = __expf(a3);
        float m0 = __shfl_sync(0xffffffffu, x0, myhead);
        float m1 = __shfl_sync(0xffffffffu, x1, myhead);
        float m2 = __shfl_sync(0xffffffffu, x2, myhead);
        float m3 = __shfl_sync(0xffffffffu, x3, myhead);

        float4 p00 = *(const float4*)&g_h[(size_t)s0 * OUTF + cb];
        float4 p01 = *(const float4*)&g_h[(size_t)s0 * OUTF + cb + 4];
        float4 p10 = *(const float4*)&g_h[(size_t)s1 * OUTF + cb];
        float4 p11 = *(const float4*)&g_h[(size_t)s1 * OUTF + cb + 4];
        float4 p20 = *(const float4*)&g_h[(size_t)s2 * OUTF + cb];
        float4 p21 = *(const float4*)&g_h[(size_t)s2 * OUTF + cb + 4];
        float4 p30 = *(const float4*)&g_h[(size_t)s3 * OUTF + cb];
        float4 p31 = *(const float4*)&g_h[(size_t)s3 * OUTF + cb + 4];

        acc0.x += m0 * p00.x; acc0.y += m0 * p00.y; acc0.z += m0 * p00.z; acc0.w += m0 * p00.w;
        acc1.x += m0 * p01.x; acc1.y += m0 * p01.y; acc1.z += m0 * p01.z; acc1.w += m0 * p01.w;
        acc0.x += m1 * p10.x; acc0.y += m1 * p10.y; acc0.z += m1 * p10.z; acc0.w += m1 * p10.w;
        acc1.x += m1 * p11.x; acc1.y += m1 * p11.y; acc1.z += m1 * p11.z; acc1.w += m1 * p11.w;
        acc0.x += m2 * p20.x; acc0.y += m2 * p20.y; acc0.z += m2 * p20.z; acc0.w += m2 * p20.w;
        acc1.x += m2 * p21.x; acc1.y += m2 * p21.y; acc1.z += m2 * p21.z; acc1.w += m2 * p21.w;
        acc0.x += m3 * p30.x; acc0.y += m3 * p30.y; acc0.z += m3 * p30.z; acc0.w += m3 * p30.w;
        acc1.x += m3 * p31.x; acc1.y += m3 * p31.y; acc1.z += m3 * p31.z; acc1.w += m3 * p31.w;
        den += m0 + m1 + m2 + m3;
    }
    for (; j < end; j++) {
        int s0 = __ldg(&g_csr[j]);
        float a0 = __ldg(&g_asrc[s0 * HEADS + h8]) + adl;
        a0 = a0 > 0.f ? a0 : NEG * a0;
        float x0 = __expf(a0);
        float m0 = __shfl_sync(0xffffffffu, x0, myhead);
        float4 p0 = *(const float4*)&g_h[(size_t)s0 * OUTF + cb];
        float4 p1 = *(const float4*)&g_h[(size_t)s0 * OUTF + cb + 4];
        acc0.x += m0 * p0.x; acc0.y += m0 * p0.y; acc0.z += m0 * p0.z; acc0.w += m0 * p0.w;
        acc1.x += m0 * p1.x; acc1.y += m0 * p1.y; acc1.z += m0 * p1.z; acc1.w += m0 * p1.w;
        den += m0;
    }

    float rden = 1.f / den;
    float4 bi0 = *(const float4*)&bias[cb];
    float4 bi1 = *(const float4*)&bias[cb + 4];
    float v[8];
    v[0] = acc0.x * rden + bi0.x; v[1] = acc0.y * rden + bi0.y;
    v[2] = acc0.z * rden + bi0.z; v[3] = acc0.w * rden + bi0.w;
    v[4] = acc1.x * rden + bi1.x; v[5] = acc1.y * rden + bi1.y;
    v[6] = acc1.z * rden + bi1.z; v[7] = acc1.w * rden + bi1.w;

    // LayerNorm over 256 via warp shuffles
    float s = 0.f, q = 0.f;
    #pragma unroll
    for (int i = 0; i < 8; i++) { s += v[i]; q += v[i] * v[i]; }
    #pragma unroll
    for (int o = 16; o; o >>= 1) {
        s += __shfl_xor_sync(0xffffffffu, s, o);
        q += __shfl_xor_sync(0xffffffffu, q, o);
    }
    float mu = s * (1.f / OUTF);
    float rstd = rsqrtf(q * (1.f / OUTF) - mu * mu + LNEPS);

    float4 ga0 = *(const float4*)&gamma[cb];
    float4 ga1 = *(const float4*)&gamma[cb + 4];
    float4 be0 = *(const float4*)&beta[cb];
    float4 be1 = *(const float4*)&beta[cb + 4];
    float4 r0, r1;
    r0.x = fmaxf((v[0] - mu) * rstd * ga0.x + be0.x, 0.f);
    r0.y = fmaxf((v[1] - mu) * rstd * ga0.y + be0.y, 0.f);
    r0.z = fmaxf((v[2] - mu) * rstd * ga0.z + be0.z, 0.f);
    r0.w = fmaxf((v[3] - mu) * rstd * ga0.w + be0.w, 0.f);
    r1.x = fmaxf((v[4] - mu) * rstd * ga1.x + be1.x, 0.f);
    r1.y = fmaxf((v[5] - mu) * rstd * ga1.y + be1.y, 0.f);
    r1.z = fmaxf((v[6] - mu) * rstd * ga1.z + be1.z, 0.f);
    r1.w = fmaxf((v[7] - mu) * rstd * ga1.w + be1.w, 0.f);
    *(float4*)&out[(size_t)d * OUTF + cb]     = r0;
    *(float4*)&out[(size_t)d * OUTF + cb + 4] = r1;
}

// ---------------- launch (fork-join: CSR build overlaps GEMM) ----------------
static cudaStream_t g_s2 = 0;
static cudaEvent_t  g_evA = 0, g_evB = 0;

extern "C" void kernel_launch(void* const* d_in, const int* in_sizes, int n_in,
                              void* d_out, int out_size) {
    const float* x       = (const float*)d_in[0];
    const int*   ei      = (const int*)d_in[1];
    const float* W       = (const float*)d_in[2];
    const float* att_src = (const float*)d_in[3];
    const float* att_dst = (const float*)d_in[4];
    const float* bias    = (const float*)d_in[5];
    const float* gamma   = (const float*)d_in[6];
    const float* beta    = (const float*)d_in[7];
    float* out = (float*)d_out;

    if (!g_s2) {   // host-side resources only; created on the uncaptured first call
        cudaStreamCreateWithFlags(&g_s2, cudaStreamNonBlocking);
        cudaEventCreateWithFlags(&g_evA, cudaEventDisableTiming);
        cudaEventCreateWithFlags(&g_evB, cudaEventDisableTiming);
    }

    // fork from the capture-origin stream
    cudaEventRecord(g_evA, 0);

    // side stream: CSR build (depends only on edge_index)
    cudaStreamWaitEvent(g_s2, g_evA, 0);
    zero_deg_kernel<<<(NN + 255) / 256, 256, 0, g_s2>>>();
    count_kernel<<<(EE / 4 + 255) / 256, 256, 0, g_s2>>>(ei);
    scan1_kernel<<<NSCAN, SCAN_BLK, 0, g_s2>>>();
    scan2_kernel<<<1, 64, 0, g_s2>>>();
    scan3_kernel<<<(NN + 255) / 256, 256, 0, g_s2>>>();
    fill_kernel<<<(EE / 4 + 255) / 256, 256, 0, g_s2>>>(ei);
    cudaEventRecord(g_evB, g_s2);

    // main stream: GEMM with fused att reduction (overlaps CSR build)
    dim3 gg((NN + 127) / 128, OUTF / 128);
    gemm_kernel<<<gg, 256>>>(x, W, att_src, att_dst);

    // join, then warp-per-node aggregate+softmax+LN
    cudaStreamWaitEvent(0, g_evB, 0);
    agg_ln_kernel<<<(NN + 7) / 8, 256>>>(out, bias, gamma, beta);
}